// round 2
// baseline (speedup 1.0000x reference)
#include <cuda_runtime.h>

#define CLASS_NUM 80
#define K_DET 300
#define MAXC 512
#define NW_MAX ((K_DET + 31) / 32)   // 10

__global__ __launch_bounds__(256) void detect_post_kernel(
    const float* __restrict__ o13, const float* __restrict__ o26, const float* __restrict__ o52,
    const float* __restrict__ a13, const float* __restrict__ a26, const float* __restrict__ a52,
    const float* __restrict__ pthresh, float* __restrict__ out)
{
    const int n   = blockIdx.x;
    const int tid = threadIdx.x;
    const int nt  = blockDim.x;
    const float thresh = *pthresh;

    __shared__ int s_cnt;
    // candidate pool (unordered)
    __shared__ float c_conf[MAXC], c_ox[MAXC], c_oy[MAXC], c_w[MAXC], c_h[MAXC];
    __shared__ int   c_cls[MAXC], c_flat[MAXC];
    // ranked (top-K_DET) arrays
    __shared__ float r_conf[K_DET], r_ox[K_DET], r_oy[K_DET], r_w[K_DET], r_h[K_DET];
    __shared__ float r_x1[K_DET], r_y1[K_DET], r_x2[K_DET], r_y2[K_DET];
    __shared__ int   r_cls[K_DET];
    __shared__ unsigned int supw[K_DET * NW_MAX];
    __shared__ unsigned char keepf[K_DET];

    if (tid == 0) s_cnt = 0;
    __syncthreads();

    // ---------------- Phase 1: decode + threshold ----------------
    const float* outs[3]   = {o13, o26, o52};
    const float* anchs[3]  = {a13, a26, a52};
    const int    Hs[3]     = {13, 26, 52};
    const float  strides[3]= {32.f, 16.f, 8.f};
    const int    bases[3]  = {0, 507, 2535};   // 13*13*3=507, +26*26*3=2028 -> 2535
    const int    Cc        = 3 * (5 + CLASS_NUM);  // 255

    for (int s = 0; s < 3; s++) {
        const int H  = Hs[s];
        const int HW = H * H;
        const float* base = outs[s] + (size_t)n * Cc * HW;
        const float stride = strides[s];
        for (int idx = tid; idx < 3 * HW; idx += nt) {
            const int a    = idx / HW;          // anchor-plane-major => coalesced conf reads
            const int cell = idx - a * HW;
            const float conf = base[(a * 85 + 0) * HW + cell];
            if (conf > thresh) {
                const int y = cell / H;
                const int x = cell - y * H;
                const float t1 = base[(a * 85 + 1) * HW + cell];
                const float t2 = base[(a * 85 + 2) * HW + cell];
                const float t3 = base[(a * 85 + 3) * HW + cell];
                const float t4 = base[(a * 85 + 4) * HW + cell];
                const float ox = ((float)x + t1) * stride;
                const float oy = ((float)y + t2) * stride;
                const float w  = expf(t3) * anchs[s][a * 2 + 0];
                const float h  = expf(t4) * anchs[s][a * 2 + 1];
                // argmax over 80 classes (first-max == jnp.argmax semantics)
                const float* cp = base + (a * 85 + 5) * HW + cell;
                float best = cp[0];
                int   bi   = 0;
                #pragma unroll 4
                for (int k = 1; k < CLASS_NUM; k++) {
                    const float v = cp[(size_t)k * HW];
                    if (v > best) { best = v; bi = k; }
                }
                const int pos = atomicAdd(&s_cnt, 1);
                if (pos < MAXC) {
                    c_conf[pos] = conf;
                    c_ox[pos]   = ox;  c_oy[pos] = oy;
                    c_w[pos]    = w;   c_h[pos]  = h;
                    c_cls[pos]  = bi;
                    c_flat[pos] = bases[s] + cell * 3 + a;  // index in concat order
                }
            }
        }
    }
    __syncthreads();
    const int V = min(s_cnt, MAXC);
    const int K = min(V, K_DET);

    // ---------------- Phase 2: rank (conf desc, tie: flat asc) ----------------
    for (int i = tid; i < V; i += nt) {
        const float ci = c_conf[i];
        const int   fi = c_flat[i];
        int r = 0;
        for (int j = 0; j < V; j++) {
            const float cj = c_conf[j];
            if (cj > ci || (cj == ci && c_flat[j] < fi)) r++;
        }
        if (r < K_DET) {
            r_conf[r] = ci;
            r_ox[r] = c_ox[i]; r_oy[r] = c_oy[i];
            r_w[r]  = c_w[i];  r_h[r]  = c_h[i];
            r_cls[r] = c_cls[i];
            const float hw = c_w[i] * 0.5f, hh = c_h[i] * 0.5f;
            r_x1[r] = c_ox[i] - hw; r_y1[r] = c_oy[i] - hh;
            r_x2[r] = c_ox[i] + hw; r_y2[r] = c_oy[i] + hh;
        }
    }
    __syncthreads();

    // ---------------- Phase 3: suppression bit-matrix ----------------
    const int NW = (K + 31) >> 5;
    for (int t = tid; t < K * NW; t += nt) {
        const int i  = t / NW;
        const int wj = t - i * NW;
        const float x1i = r_x1[i], y1i = r_y1[i], x2i = r_x2[i], y2i = r_y2[i];
        const float areai = (x2i - x1i) * (y2i - y1i);
        const int   ci = r_cls[i];
        unsigned int word = 0;
        const int jmax = min(K, (wj + 1) * 32);
        for (int j = wj * 32; j < jmax; j++) {
            if (r_cls[j] != ci) continue;
            const float ix1 = fmaxf(x1i, r_x1[j]);
            const float iy1 = fmaxf(y1i, r_y1[j]);
            const float ix2 = fminf(x2i, r_x2[j]);
            const float iy2 = fminf(y2i, r_y2[j]);
            const float iw = fmaxf(ix2 - ix1, 0.f);
            const float ih = fmaxf(iy2 - iy1, 0.f);
            const float inter = iw * ih;
            const float areaj = (r_x2[j] - r_x1[j]) * (r_y2[j] - r_y1[j]);
            const float uni   = fmaxf(areai + areaj - inter, 1e-9f);
            if (inter / uni > 0.3f) word |= (1u << (j & 31));
        }
        supw[i * NW + wj] = word;
    }
    __syncthreads();

    // ---------------- Phase 3b: sequential greedy NMS scan ----------------
    if (tid == 0) {
        unsigned int kw[NW_MAX];
        #pragma unroll
        for (int w = 0; w < NW_MAX; w++) kw[w] = 0u;
        for (int i = 0; i < K; i++) {
            unsigned int sup = 0;
            for (int w = 0; w < NW; w++) sup |= kw[w] & supw[i * NW + w];
            if (sup == 0u) {
                kw[i >> 5] |= (1u << (i & 31));
                keepf[i] = 1;
            } else {
                keepf[i] = 0;
            }
        }
    }
    __syncthreads();

    // ---------------- Phase 4: write output (all 300x7 per image) ----------------
    const float fn = (float)n;
    float* orow = out + (size_t)n * (K_DET * 7);
    for (int e = tid; e < K_DET * 7; e += nt) {
        const int i = e / 7;
        const int f = e - i * 7;
        float v = 0.f;
        if (i < K && keepf[i]) {
            switch (f) {
                case 0: v = r_conf[i]; break;
                case 1: v = r_ox[i];   break;
                case 2: v = r_oy[i];   break;
                case 3: v = r_w[i];    break;
                case 4: v = r_h[i];    break;
                case 5: v = (float)r_cls[i]; break;
                case 6: v = fn;        break;
            }
        }
        orow[e] = v;
    }
}

extern "C" void kernel_launch(void* const* d_in, const int* in_sizes, int n_in,
                              void* d_out, int out_size) {
    const float* o13 = (const float*)d_in[0];
    const float* o26 = (const float*)d_in[1];
    const float* o52 = (const float*)d_in[2];
    const float* a13 = (const float*)d_in[3];
    const float* a26 = (const float*)d_in[4];
    const float* a52 = (const float*)d_in[5];
    const float* thr = (const float*)d_in[6];
    float* out = (float*)d_out;

    const int N = in_sizes[0] / (255 * 13 * 13);   // batch size (=64)
    detect_post_kernel<<<N, 256>>>(o13, o26, o52, a13, a26, a52, thr, out);
}

// round 3
// speedup vs baseline: 2.0656x; 2.0656x over previous
#include <cuda_runtime.h>

#define CLASS_NUM 80
#define K_DET 300
#define MAXC 512
#define NW_MAX ((K_DET + 31) / 32)   // 10
#define MAX_IMG 256

// ---- global scratch (per-image candidate pools) ----
__device__ int   g_cnt[MAX_IMG];          // zero-initialized at module load
__device__ float g_conf[MAX_IMG * MAXC];
__device__ float g_ox  [MAX_IMG * MAXC];
__device__ float g_oy  [MAX_IMG * MAXC];
__device__ float g_w   [MAX_IMG * MAXC];
__device__ float g_h   [MAX_IMG * MAXC];
__device__ int   g_cls [MAX_IMG * MAXC];
__device__ int   g_flat[MAX_IMG * MAXC];

// ================= Kernel A: full-chip scan + decode =================
__global__ __launch_bounds__(256) void scan_kernel(
    const float* __restrict__ o13, const float* __restrict__ o26, const float* __restrict__ o52,
    const float* __restrict__ a13, const float* __restrict__ a26, const float* __restrict__ a52,
    const float* __restrict__ pthresh, int total_per_img)
{
    const int gid = blockIdx.x * blockDim.x + threadIdx.x;
    const int n   = gid / total_per_img;          // image
    const int idx = gid - n * total_per_img;      // [0, 10647)
    if (gid >= gridDim.x * blockDim.x) return;    // (never; kept simple)

    const float thresh = *pthresh;

    // resolve scale
    int s, base_off, H;
    const float* tensor; const float* anch; float stride;
    if (idx < 507)        { s = 0; base_off = 0;    H = 13; tensor = o13; anch = a13; stride = 32.f; }
    else if (idx < 2535)  { s = 1; base_off = 507;  H = 26; tensor = o26; anch = a26; stride = 16.f; }
    else                  { s = 2; base_off = 2535; H = 52; tensor = o52; anch = a52; stride = 8.f;  }
    (void)s;
    const int HW    = H * H;
    const int idxp  = idx - base_off;             // [0, 3*HW)
    const int a     = idxp / HW;                  // anchor-plane-major -> coalesced conf
    const int cell  = idxp - a * HW;

    const float* base = tensor + (size_t)n * (3 * (5 + CLASS_NUM)) * HW;
    const float conf  = base[(a * 85 + 0) * HW + cell];
    if (conf > thresh) {
        const int y = cell / H;
        const int x = cell - y * H;
        const float t1 = base[(a * 85 + 1) * HW + cell];
        const float t2 = base[(a * 85 + 2) * HW + cell];
        const float t3 = base[(a * 85 + 3) * HW + cell];
        const float t4 = base[(a * 85 + 4) * HW + cell];
        const float ox = ((float)x + t1) * stride;
        const float oy = ((float)y + t2) * stride;
        const float w  = expf(t3) * anch[a * 2 + 0];
        const float h  = expf(t4) * anch[a * 2 + 1];
        // first-max argmax over 80 classes
        const float* cp = base + (a * 85 + 5) * HW + cell;
        float best = cp[0];
        int   bi   = 0;
        #pragma unroll 8
        for (int k = 1; k < CLASS_NUM; k++) {
            const float v = cp[(size_t)k * HW];
            if (v > best) { best = v; bi = k; }
        }
        const int pos = atomicAdd(&g_cnt[n], 1);
        if (pos < MAXC) {
            const int o = n * MAXC + pos;
            g_conf[o] = conf;
            g_ox[o]   = ox;  g_oy[o] = oy;
            g_w[o]    = w;   g_h[o]  = h;
            g_cls[o]  = bi;
            g_flat[o] = base_off + cell * 3 + a;   // concat-order index (tie-break)
        }
    }
}

// ================= Kernel B: per-image rank + NMS + write =================
__global__ __launch_bounds__(256) void nms_kernel(float* __restrict__ out)
{
    const int n   = blockIdx.x;
    const int tid = threadIdx.x;
    const int nt  = blockDim.x;

    __shared__ float c_conf[MAXC], c_ox[MAXC], c_oy[MAXC], c_w[MAXC], c_h[MAXC];
    __shared__ int   c_cls[MAXC], c_flat[MAXC];
    __shared__ float r_conf[K_DET], r_ox[K_DET], r_oy[K_DET], r_w[K_DET], r_h[K_DET];
    __shared__ float r_x1[K_DET], r_y1[K_DET], r_x2[K_DET], r_y2[K_DET];
    __shared__ int   r_cls[K_DET];
    __shared__ unsigned int supw[K_DET * NW_MAX];
    __shared__ unsigned char keepf[K_DET];

    const int V = min(g_cnt[n], MAXC);
    const int K = min(V, K_DET);

    // load candidate pool into shared
    for (int i = tid; i < V; i += nt) {
        const int o = n * MAXC + i;
        c_conf[i] = g_conf[o];
        c_ox[i]   = g_ox[o];  c_oy[i] = g_oy[o];
        c_w[i]    = g_w[o];   c_h[i]  = g_h[o];
        c_cls[i]  = g_cls[o];
        c_flat[i] = g_flat[o];
    }
    __syncthreads();

    // rank (conf desc, tie: flat asc)
    for (int i = tid; i < V; i += nt) {
        const float ci = c_conf[i];
        const int   fi = c_flat[i];
        int r = 0;
        for (int j = 0; j < V; j++) {
            const float cj = c_conf[j];
            if (cj > ci || (cj == ci && c_flat[j] < fi)) r++;
        }
        if (r < K_DET) {
            r_conf[r] = ci;
            r_ox[r] = c_ox[i]; r_oy[r] = c_oy[i];
            r_w[r]  = c_w[i];  r_h[r]  = c_h[i];
            r_cls[r] = c_cls[i];
            const float hw = c_w[i] * 0.5f, hh = c_h[i] * 0.5f;
            r_x1[r] = c_ox[i] - hw; r_y1[r] = c_oy[i] - hh;
            r_x2[r] = c_ox[i] + hw; r_y2[r] = c_oy[i] + hh;
        }
    }
    __syncthreads();

    // suppression bit-matrix
    const int NW = (K + 31) >> 5;
    for (int t = tid; t < K * NW; t += nt) {
        const int i  = t / NW;
        const int wj = t - i * NW;
        const float x1i = r_x1[i], y1i = r_y1[i], x2i = r_x2[i], y2i = r_y2[i];
        const float areai = (x2i - x1i) * (y2i - y1i);
        const int   ci = r_cls[i];
        unsigned int word = 0;
        const int jmax = min(K, (wj + 1) * 32);
        for (int j = wj * 32; j < jmax; j++) {
            if (r_cls[j] != ci) continue;
            const float ix1 = fmaxf(x1i, r_x1[j]);
            const float iy1 = fmaxf(y1i, r_y1[j]);
            const float ix2 = fminf(x2i, r_x2[j]);
            const float iy2 = fminf(y2i, r_y2[j]);
            const float iw = fmaxf(ix2 - ix1, 0.f);
            const float ih = fmaxf(iy2 - iy1, 0.f);
            const float inter = iw * ih;
            const float areaj = (r_x2[j] - r_x1[j]) * (r_y2[j] - r_y1[j]);
            const float uni   = fmaxf(areai + areaj - inter, 1e-9f);
            if (inter / uni > 0.3f) word |= (1u << (j & 31));
        }
        supw[i * NW + wj] = word;
    }
    __syncthreads();

    // sequential greedy scan
    if (tid == 0) {
        unsigned int kw[NW_MAX];
        #pragma unroll
        for (int w = 0; w < NW_MAX; w++) kw[w] = 0u;
        for (int i = 0; i < K; i++) {
            unsigned int sup = 0;
            for (int w = 0; w < NW; w++) sup |= kw[w] & supw[i * NW + w];
            if (sup == 0u) {
                kw[i >> 5] |= (1u << (i & 31));
                keepf[i] = 1;
            } else {
                keepf[i] = 0;
            }
        }
        g_cnt[n] = 0;   // reset for next graph replay (deterministic)
    }
    __syncthreads();

    // write output (all 300x7, zeros where not kept; d_out is poisoned)
    const float fn = (float)n;
    float* orow = out + (size_t)n * (K_DET * 7);
    for (int e = tid; e < K_DET * 7; e += nt) {
        const int i = e / 7;
        const int f = e - i * 7;
        float v = 0.f;
        if (i < K && keepf[i]) {
            switch (f) {
                case 0: v = r_conf[i]; break;
                case 1: v = r_ox[i];   break;
                case 2: v = r_oy[i];   break;
                case 3: v = r_w[i];    break;
                case 4: v = r_h[i];    break;
                case 5: v = (float)r_cls[i]; break;
                case 6: v = fn;        break;
            }
        }
        orow[e] = v;
    }
}

extern "C" void kernel_launch(void* const* d_in, const int* in_sizes, int n_in,
                              void* d_out, int out_size) {
    const float* o13 = (const float*)d_in[0];
    const float* o26 = (const float*)d_in[1];
    const float* o52 = (const float*)d_in[2];
    const float* a13 = (const float*)d_in[3];
    const float* a26 = (const float*)d_in[4];
    const float* a52 = (const float*)d_in[5];
    const float* thr = (const float*)d_in[6];
    float* out = (float*)d_out;

    const int N = in_sizes[0] / (255 * 13 * 13);   // batch (=64)
    const int total_per_img = 3 * (13*13 + 26*26 + 52*52);  // 10647
    const int total = N * total_per_img;

    scan_kernel<<<(total + 255) / 256, 256>>>(o13, o26, o52, a13, a26, a52, thr, total_per_img);
    nms_kernel<<<N, 256>>>(out);
}